// round 12
// baseline (speedup 1.0000x reference)
#include <cuda_runtime.h>
#include <math.h>
#include <stdint.h>

#define NT   8192        // tiles: bs(8) * n(32) * n(32)
#define NSM  148         // sm_100a
#define GRID NSM         // 1 CTA/SM persistent

static __device__ float g_P[64 * 256];     // P[pair][c], pair = m1*8+m2

// ---------------------------------------------------------------------------
// Kernel 1: P[p][c] = sum_d pe[p][d] * W[c][d]   (64 blocks, ~2-3 us)
// ---------------------------------------------------------------------------
__global__ void __launch_bounds__(256) compute_P_kernel(const float* __restrict__ W)
{
    __shared__ float pe[64];
    const int tid = threadIdx.x;
    const int p   = blockIdx.x;

    float4 w4[16];
    const float4* wp = (const float4*)(W + tid * 64);
#pragma unroll
    for (int i = 0; i < 16; ++i) w4[i] = wp[i];

    if (tid < 32) {
        float div = expf(-(float)tid * 0.28782313662425572f); // ln(1e4)/32
        float ang = (float)p * div;
        pe[2 * tid]     = sinf(ang);
        pe[2 * tid + 1] = cosf(ang);
    }
    __syncthreads();

    float a0 = 0.f, a1 = 0.f, a2 = 0.f, a3 = 0.f;
#pragma unroll
    for (int i = 0; i < 16; ++i) {
        a0 = fmaf(pe[4 * i + 0], w4[i].x, a0);
        a1 = fmaf(pe[4 * i + 1], w4[i].y, a1);
        a2 = fmaf(pe[4 * i + 2], w4[i].z, a2);
        a3 = fmaf(pe[4 * i + 3], w4[i].w, a3);
    }
    g_P[p * 256 + tid] = (a0 + a1) + (a2 + a3);
}

// ---------------------------------------------------------------------------
// Kernel 2: fused persistent GEMV + TMA-bulk-store kernel, GEMV overlapped.
//
// Loop invariant at iteration top (tile t, flag cur):
//   av[cur]     = a(t)          (GEMV result, ready)
//   ea[cur^1]   = E row of t+1  (ready)
//   m1v/m2v     = masks of t,  m1n/m2n = masks of t+1
//
// Phase X (one barrier region): STS tile t from av[cur] into TMA buffer
//   || GEMV(t+1): ea[cur^1] -> av[cur^1]   (tid < 256)
//   || E-prefetch(t+2) -> ea[cur]          (tid 256..271)
//   || mask prefetch (t+2) -> registers
// syncB; tid0: fence + 8 x 8KB cp.async.bulk + commit + wait_group 1; syncA.
//
// SMEM (floats): Wt[0,16448) pad-257 W^T | ea[16448,16576) 2x64 |
//                av[16576,17088) 2x256 | bufs[17088,49856) 2x16384
// ---------------------------------------------------------------------------
__global__ void __launch_bounds__(512, 1) etoc_fused_kernel(
    const float* __restrict__ E,
    const float* __restrict__ m1g,
    const float* __restrict__ m2g,
    const float* __restrict__ Wg,
    float* __restrict__ out)
{
    extern __shared__ float sm[];
    float* Wt   = sm;                 // 64 * 257
    float* ea   = sm + 16448;         // 2 * 64
    float* av   = sm + 16576;         // 2 * 256
    float* bufs = sm + 17088;         // 2 * 16384

    const int tid = threadIdx.x;
    const int cq  = tid & 63;         // float4 column index (c/4)
    const int grp = tid >> 6;         // m2 index 0..7

    // Stage W transposed, pad-257 (coalesced LDG, conflict-free LDS).
    for (int idx = tid; idx < 16384; idx += 512) {
        int c = idx >> 6, d = idx & 63;
        Wt[d * 257 + c] = Wg[idx];
    }

    // P slice in registers
    float4 Pr[8];
#pragma unroll
    for (int m1 = 0; m1 < 8; ++m1)
        Pr[m1] = *(const float4*)(g_P + (m1 * 8 + grp) * 256 + 4 * cq);

    int t = blockIdx.x;
    int b  = t >> 10, i1 = (t >> 5) & 31, j1 = t & 31;

    // Prologue 1: E row of t into ea[0]; masks of t.
    if (tid < 16)
        ((float4*)ea)[tid] = ((const float4*)(E + t * 64))[tid];
    float m1v = __ldg(m1g + b * 32 + i1);
    float m2v = __ldg(m2g + b * 32 + ((j1 * 8 + grp) & 31));
    __syncthreads();

    // Prologue 2: GEMV(t) -> av[0]; E(t+1) -> ea[1]; masks of t+1.
    {
        int tn = t + GRID;
        if (tid < 256) {
            const float4* e4 = (const float4*)ea;
            float a0 = 0.f, a1 = 0.f, a2 = 0.f, a3 = 0.f;
#pragma unroll
            for (int i = 0; i < 16; ++i) {
                float4 e = e4[i];
                a0 = fmaf(e.x, Wt[(4 * i + 0) * 257 + tid], a0);
                a1 = fmaf(e.y, Wt[(4 * i + 1) * 257 + tid], a1);
                a2 = fmaf(e.z, Wt[(4 * i + 2) * 257 + tid], a2);
                a3 = fmaf(e.w, Wt[(4 * i + 3) * 257 + tid], a3);
            }
            av[tid] = (a0 + a1) + (a2 + a3);
        } else if (tn < NT && tid < 272) {
            ((float4*)(ea + 64))[tid - 256] =
                ((const float4*)(E + tn * 64))[tid - 256];
        }
    }
    float m1n = 0.f, m2n = 0.f;
    if (t + GRID < NT) {
        int tn = t + GRID;
        int bn = tn >> 10, i1n = (tn >> 5) & 31, j1n = tn & 31;
        m1n = __ldg(m1g + bn * 32 + i1n);
        m2n = __ldg(m2g + bn * 32 + ((j1n * 8 + grp) & 31));
    }
    __syncthreads();   // plays the role of syncA for the first iteration

    int it = 0, cur = 0;
    while (true) {
        float* buf = bufs + (it & 1) * 16384;
        int  tn   = t + GRID;
        int  tnn  = t + 2 * GRID;
        bool more = tn < NT;

        // ---- Phase X: STS(t)  ||  GEMV(t+1)  ||  prefetch(t+2) ----
        float  f  = m1v * m2v;
        float4 a4 = *(const float4*)(av + cur * 256 + 4 * cq);
        float4 fa = {f * a4.x, f * a4.y, f * a4.z, f * a4.w};
#pragma unroll
        for (int m1 = 0; m1 < 8; ++m1) {
            float4 p = Pr[m1];
            float4 v;
            v.x = fmaf(f, p.x, fa.x);
            v.y = fmaf(f, p.y, fa.y);
            v.z = fmaf(f, p.z, fa.z);
            v.w = fmaf(f, p.w, fa.w);
            *(float4*)(buf + m1 * 2048 + grp * 256 + 4 * cq) = v;
        }

        float m1nn = 0.f, m2nn = 0.f;
        if (more) {
            // GEMV for t+1 (overlapped with the STS burst above)
            if (tid < 256) {
                const float4* e4 = (const float4*)(ea + (cur ^ 1) * 64);
                float a0 = 0.f, a1 = 0.f, a2 = 0.f, a3 = 0.f;
#pragma unroll
                for (int i = 0; i < 16; ++i) {
                    float4 e = e4[i];
                    a0 = fmaf(e.x, Wt[(4 * i + 0) * 257 + tid], a0);
                    a1 = fmaf(e.y, Wt[(4 * i + 1) * 257 + tid], a1);
                    a2 = fmaf(e.z, Wt[(4 * i + 2) * 257 + tid], a2);
                    a3 = fmaf(e.w, Wt[(4 * i + 3) * 257 + tid], a3);
                }
                av[(cur ^ 1) * 256 + tid] = (a0 + a1) + (a2 + a3);
            } else if (tnn < NT && tid < 272) {
                ((float4*)(ea + cur * 64))[tid - 256] =
                    ((const float4*)(E + tnn * 64))[tid - 256];
            }
            if (tnn < NT) {
                int bn = tnn >> 10, i1n = (tnn >> 5) & 31, j1n = tnn & 31;
                m1nn = __ldg(m1g + bn * 32 + i1n);
                m2nn = __ldg(m2g + bn * 32 + ((j1n * 8 + grp) & 31));
            }
        }
        __syncthreads();   // syncB: buf complete, av[nxt] complete

        // ---- TMA issue for tile t + pipeline throttle ----
        if (tid == 0) {
            asm volatile("fence.proxy.async.shared::cta;" ::: "memory");
            uint32_t s0;
            asm("{ .reg .u64 tt; cvta.to.shared.u64 tt, %1; cvt.u32.u64 %0, tt; }"
                : "=r"(s0) : "l"(buf));
            float* g0 = out +
                ((long)((b * 256 + i1 * 8) * 256 + j1 * 8)) * 256;
#pragma unroll
            for (int m1 = 0; m1 < 8; ++m1) {
                asm volatile(
                    "cp.async.bulk.global.shared::cta.bulk_group [%0], [%1], %2;"
                    :: "l"(g0 + (long)m1 * 65536), "r"(s0 + m1 * 8192),
                       "r"(8192u)
                    : "memory");
            }
            asm volatile("cp.async.bulk.commit_group;" ::: "memory");
            // <=1 group pending -> group it-1 done -> other buffer free
            asm volatile("cp.async.bulk.wait_group 1;" ::: "memory");
        }

        if (!more) break;
        t = tn;
        b = t >> 10; i1 = (t >> 5) & 31; j1 = t & 31;
        m1v = m1n; m2v = m2n;
        m1n = m1nn; m2n = m2nn;
        cur ^= 1; ++it;
        __syncthreads();   // syncA: buffer freed by wait_group, safe to STS
    }

    // Drain all pending bulk stores before SMEM is released.
    if (tid == 0)
        asm volatile("cp.async.bulk.wait_group 0;" ::: "memory");
    __syncthreads();
}

// ---------------------------------------------------------------------------
// Launch
// ---------------------------------------------------------------------------
extern "C" void kernel_launch(void* const* d_in, const int* in_sizes, int n_in,
                              void* d_out, int out_size) {
    const float* E  = (const float*)d_in[0];  // (8,32,32,64)
    const float* m1 = (const float*)d_in[1];  // (8,32,1,1)
    const float* m2 = (const float*)d_in[2];  // (8,1,32,1)
    const float* W  = (const float*)d_in[3];  // (256,64)

    compute_P_kernel<<<64, 256>>>(W);

    size_t smem_bytes = 49856 * sizeof(float);   // 199424 B
    cudaFuncSetAttribute(etoc_fused_kernel,
                         cudaFuncAttributeMaxDynamicSharedMemorySize,
                         (int)smem_bytes);
    etoc_fused_kernel<<<GRID, 512, smem_bytes>>>(E, m1, m2, W, (float*)d_out);
}